// round 1
// baseline (speedup 1.0000x reference)
#include <cuda_runtime.h>

#define NROWS 32768
#define BSZ   1024
#define AGN   32
#define IND   96
#define HDIM  64
#define NNHD  64
#define ATTD  32
#define NACTD 16
#define LDIM  16
#define DLAT  512

// ---------------- scratch (device globals; no runtime allocation) ----------------
__device__ float g_z1[NROWS * NNHD];
__device__ float g_q[NROWS * NACTD];
__device__ float g_query[NROWS * ATTD];
__device__ float g_m1h[NROWS * NNHD];
__device__ float g_lat[BSZ * AGN * AGN * LDIM];   // layout [b][j][i][l]
__device__ float g_alpha[BSZ * AGN * AGN];        // layout [b][j][i]
__device__ float g_bn_a[NNHD];
__device__ float g_bn_c[NNHD];

// ---------------- helpers ----------------
__device__ __forceinline__ float dot64r(const float* __restrict__ w, const float (&z)[64]) {
    const float4* w4 = reinterpret_cast<const float4*>(w);
    float a0 = 0.f, a1 = 0.f;
#pragma unroll
    for (int k = 0; k < 16; k += 2) {
        float4 u = __ldg(w4 + k);
        float4 v = __ldg(w4 + k + 1);
        a0 = fmaf(u.x, z[4*k+0], a0); a0 = fmaf(u.y, z[4*k+1], a0);
        a0 = fmaf(u.z, z[4*k+2], a0); a0 = fmaf(u.w, z[4*k+3], a0);
        a1 = fmaf(v.x, z[4*k+4], a1); a1 = fmaf(v.y, z[4*k+5], a1);
        a1 = fmaf(v.z, z[4*k+6], a1); a1 = fmaf(v.w, z[4*k+7], a1);
    }
    return a0 + a1;
}

__device__ __forceinline__ float dot96r(const float* __restrict__ w, const float (&z)[96]) {
    const float4* w4 = reinterpret_cast<const float4*>(w);
    float a0 = 0.f, a1 = 0.f;
#pragma unroll
    for (int k = 0; k < 24; k += 2) {
        float4 u = __ldg(w4 + k);
        float4 v = __ldg(w4 + k + 1);
        a0 = fmaf(u.x, z[4*k+0], a0); a0 = fmaf(u.y, z[4*k+1], a0);
        a0 = fmaf(u.z, z[4*k+2], a0); a0 = fmaf(u.w, z[4*k+3], a0);
        a1 = fmaf(v.x, z[4*k+4], a1); a1 = fmaf(v.y, z[4*k+5], a1);
        a1 = fmaf(v.z, z[4*k+6], a1); a1 = fmaf(v.w, z[4*k+7], a1);
    }
    return a0 + a1;
}

__device__ __forceinline__ float sigmoidf_(float x) { return 1.f / (1.f + expf(-x)); }

// ---------------- K1: fused trunk ----------------
// x = relu(fc1(in)); GRU -> h; heads: q, z1, query(scaled), msg1_h; h -> d_out
__global__ void __launch_bounds__(128) k1_trunk(
    const float* __restrict__ inp, const float* __restrict__ h0,
    const float* __restrict__ fc1_w, const float* __restrict__ fc1_b,
    const float* __restrict__ wih, const float* __restrict__ whh,
    const float* __restrict__ bih, const float* __restrict__ bhh,
    const float* __restrict__ fc2_w, const float* __restrict__ fc2_b,
    const float* __restrict__ emb_w1, const float* __restrict__ emb_b1,
    const float* __restrict__ wq_w, const float* __restrict__ wq_b,
    const float* __restrict__ msg_w1, const float* __restrict__ msg_b1,
    float* __restrict__ h_out)
{
    extern __shared__ float sm1[];
    float* sX  = sm1;             // 128 * 65
    float* sHn = sm1 + 128 * 65;  // 128 * 65
    const int tid = threadIdx.x;
    const int row = blockIdx.x * 128 + tid;

    // input row -> regs
    float xin[IND];
    {
        const float4* ip = reinterpret_cast<const float4*>(inp + (size_t)row * IND);
#pragma unroll
        for (int k = 0; k < IND / 4; k++) {
            float4 v = __ldg(ip + k);
            xin[4*k] = v.x; xin[4*k+1] = v.y; xin[4*k+2] = v.z; xin[4*k+3] = v.w;
        }
    }
    // h0 -> regs
    float hr[HDIM];
    {
        const float4* hp = reinterpret_cast<const float4*>(h0 + (size_t)row * HDIM);
#pragma unroll
        for (int k = 0; k < 16; k++) {
            float4 v = __ldg(hp + k);
            hr[4*k] = v.x; hr[4*k+1] = v.y; hr[4*k+2] = v.z; hr[4*k+3] = v.w;
        }
    }
    float* myX  = sX  + tid * 65;
    float* myHn = sHn + tid * 65;

    // fc1 + relu (dynamic o-loop writes to smem, then unrolled copy to regs)
    for (int o = 0; o < HDIM; o++) {
        float acc = __ldg(fc1_b + o) + dot96r(fc1_w + o * IND, xin);
        myX[o] = fmaxf(acc, 0.f);
    }
    float xr[64];
#pragma unroll
    for (int k = 0; k < 64; k++) xr[k] = myX[k];

    // GRU: fused r/z/n per output; new h written to sHn (cannot overwrite hr mid-loop)
    for (int o = 0; o < HDIM; o++) {
        float ar = __ldg(bih + o) + __ldg(bhh + o)
                 + dot64r(wih + o * HDIM, xr) + dot64r(whh + o * HDIM, hr);
        float az = __ldg(bih + HDIM + o) + __ldg(bhh + HDIM + o)
                 + dot64r(wih + (HDIM + o) * HDIM, xr) + dot64r(whh + (HDIM + o) * HDIM, hr);
        float ai = __ldg(bih + 2 * HDIM + o) + dot64r(wih + (2 * HDIM + o) * HDIM, xr);
        float ah = __ldg(bhh + 2 * HDIM + o) + dot64r(whh + (2 * HDIM + o) * HDIM, hr);
        float r = sigmoidf_(ar);
        float z = sigmoidf_(az);
        float n = tanhf(ai + r * ah);
        myHn[o] = (1.f - z) * n + z * hr[o];
    }
#pragma unroll
    for (int k = 0; k < 64; k++) hr[k] = myHn[k];

    // h out
    {
        float4* hop = reinterpret_cast<float4*>(h_out + (size_t)row * HDIM);
#pragma unroll
        for (int k = 0; k < 16; k++)
            hop[k] = make_float4(hr[4*k], hr[4*k+1], hr[4*k+2], hr[4*k+3]);
    }
    // q (16)
    {
        float4* dst = reinterpret_cast<float4*>(g_q + (size_t)row * NACTD);
        for (int o4 = 0; o4 < 4; o4++) {
            float v0 = __ldg(fc2_b + 4*o4+0) + dot64r(fc2_w + (4*o4+0) * HDIM, hr);
            float v1 = __ldg(fc2_b + 4*o4+1) + dot64r(fc2_w + (4*o4+1) * HDIM, hr);
            float v2 = __ldg(fc2_b + 4*o4+2) + dot64r(fc2_w + (4*o4+2) * HDIM, hr);
            float v3 = __ldg(fc2_b + 4*o4+3) + dot64r(fc2_w + (4*o4+3) * HDIM, hr);
            dst[o4] = make_float4(v0, v1, v2, v3);
        }
    }
    // z1 (64, pre-BN)
    {
        float4* dst = reinterpret_cast<float4*>(g_z1 + (size_t)row * NNHD);
        for (int o4 = 0; o4 < 16; o4++) {
            float v0 = __ldg(emb_b1 + 4*o4+0) + dot64r(emb_w1 + (4*o4+0) * HDIM, hr);
            float v1 = __ldg(emb_b1 + 4*o4+1) + dot64r(emb_w1 + (4*o4+1) * HDIM, hr);
            float v2 = __ldg(emb_b1 + 4*o4+2) + dot64r(emb_w1 + (4*o4+2) * HDIM, hr);
            float v3 = __ldg(emb_b1 + 4*o4+3) + dot64r(emb_w1 + (4*o4+3) * HDIM, hr);
            dst[o4] = make_float4(v0, v1, v2, v3);
        }
    }
    // query (32), pre-scaled by 1/sqrt(32)
    {
        const float qs = 0.17677669529663687f;
        float4* dst = reinterpret_cast<float4*>(g_query + (size_t)row * ATTD);
        for (int o4 = 0; o4 < 8; o4++) {
            float v0 = (__ldg(wq_b + 4*o4+0) + dot64r(wq_w + (4*o4+0) * HDIM, hr)) * qs;
            float v1 = (__ldg(wq_b + 4*o4+1) + dot64r(wq_w + (4*o4+1) * HDIM, hr)) * qs;
            float v2 = (__ldg(wq_b + 4*o4+2) + dot64r(wq_w + (4*o4+2) * HDIM, hr)) * qs;
            float v3 = (__ldg(wq_b + 4*o4+3) + dot64r(wq_w + (4*o4+3) * HDIM, hr)) * qs;
            dst[o4] = make_float4(v0, v1, v2, v3);
        }
    }
    // msg layer-1 h-contribution (64): msg_w1 rows stride 80, first 64 cols
    {
        float4* dst = reinterpret_cast<float4*>(g_m1h + (size_t)row * NNHD);
        for (int o4 = 0; o4 < 16; o4++) {
            float v0 = __ldg(msg_b1 + 4*o4+0) + dot64r(msg_w1 + (4*o4+0) * 80, hr);
            float v1 = __ldg(msg_b1 + 4*o4+1) + dot64r(msg_w1 + (4*o4+1) * 80, hr);
            float v2 = __ldg(msg_b1 + 4*o4+2) + dot64r(msg_w1 + (4*o4+2) * 80, hr);
            float v3 = __ldg(msg_b1 + 4*o4+3) + dot64r(msg_w1 + (4*o4+3) * 80, hr);
            dst[o4] = make_float4(v0, v1, v2, v3);
        }
    }
}

// ---------------- K2: BN statistics (deterministic reduction, one block per feature) ----------------
__global__ void __launch_bounds__(256) k2_bn(const float* __restrict__ bn_g,
                                             const float* __restrict__ bn_b)
{
    __shared__ float ss[256], sq[256];
    const int f = blockIdx.x;
    const int tid = threadIdx.x;
    float s = 0.f, q = 0.f;
    for (int n = tid; n < NROWS; n += 256) {
        float v = g_z1[(size_t)n * NNHD + f];
        s += v; q += v * v;
    }
    ss[tid] = s; sq[tid] = q;
    __syncthreads();
    for (int st = 128; st > 0; st >>= 1) {
        if (tid < st) { ss[tid] += ss[tid + st]; sq[tid] += sq[tid + st]; }
        __syncthreads();
    }
    if (tid == 0) {
        float mean = ss[0] * (1.f / (float)NROWS);
        float var  = sq[0] * (1.f / (float)NROWS) - mean * mean;
        float a = __ldg(bn_g + f) / sqrtf(var + 1e-5f);
        g_bn_a[f] = a;
        g_bn_c[f] = __ldg(bn_b + f) - a * mean;
    }
}

// ---------------- K3: latent + keys + masked softmax (one thread per (b,i) row) ----------------
__global__ void __launch_bounds__(128) k3_latent(
    const float* __restrict__ eps,
    const float* __restrict__ emb_w2, const float* __restrict__ emb_b2,
    const float* __restrict__ wk_w, const float* __restrict__ wk_b)
{
    __shared__ float sQ[128 * 33];    // query tile
    __shared__ float sLat[128 * 17];  // per-thread latent chunk (16) for key stage
    __shared__ float sAl[128 * 33];   // per-thread alpha row (32)
    const int tid = threadIdx.x;
    const int row0 = blockIdx.x * 128;
    const int row = row0 + tid;
    const int b = row >> 5;
    const int i = row & 31;

    for (int idx = tid; idx < 128 * 32; idx += 128) {
        int r = idx >> 5, c = idx & 31;
        sQ[r * 33 + c] = g_query[(size_t)(row0 + r) * ATTD + c];
    }
    __syncthreads();

    // z1 -> BN affine -> lrelu -> regs
    float zr[64];
    {
        const float4* zp = reinterpret_cast<const float4*>(g_z1 + (size_t)row * NNHD);
#pragma unroll
        for (int k = 0; k < 16; k++) {
            float4 v = __ldg(zp + k);
            float t;
            t = g_bn_a[4*k+0] * v.x + g_bn_c[4*k+0]; zr[4*k+0] = t > 0.f ? t : 0.01f * t;
            t = g_bn_a[4*k+1] * v.y + g_bn_c[4*k+1]; zr[4*k+1] = t > 0.f ? t : 0.01f * t;
            t = g_bn_a[4*k+2] * v.z + g_bn_c[4*k+2]; zr[4*k+2] = t > 0.f ? t : 0.01f * t;
            t = g_bn_a[4*k+3] * v.w + g_bn_c[4*k+3]; zr[4*k+3] = t > 0.f ? t : 0.01f * t;
        }
    }

    float* myLat = sLat + tid * 17;
    float* myAl  = sAl  + tid * 33;
    const float* qv = sQ + tid * 33;

    for (int j = 0; j < AGN; j++) {
        const float4* e4 = reinterpret_cast<const float4*>(eps + (size_t)row * DLAT + j * LDIM);
        float4* outp = reinterpret_cast<float4*>(g_lat + ((size_t)(b * AGN + j) * AGN + i) * LDIM);
        for (int l4 = 0; l4 < 4; l4++) {
            float4 ev = __ldg(e4 + l4);
            int d = j * LDIM + l4 * 4;
            float4 lv4;
            {
                float mu = __ldg(emb_b2 + d + 0) + dot64r(emb_w2 + (d + 0) * 64, zr);
                float lg = __ldg(emb_b2 + DLAT + d + 0) + dot64r(emb_w2 + (DLAT + d + 0) * 64, zr);
                lv4.x = mu + sqrtf(fmaxf(expf(lg), 0.002f)) * ev.x;
            }
            {
                float mu = __ldg(emb_b2 + d + 1) + dot64r(emb_w2 + (d + 1) * 64, zr);
                float lg = __ldg(emb_b2 + DLAT + d + 1) + dot64r(emb_w2 + (DLAT + d + 1) * 64, zr);
                lv4.y = mu + sqrtf(fmaxf(expf(lg), 0.002f)) * ev.y;
            }
            {
                float mu = __ldg(emb_b2 + d + 2) + dot64r(emb_w2 + (d + 2) * 64, zr);
                float lg = __ldg(emb_b2 + DLAT + d + 2) + dot64r(emb_w2 + (DLAT + d + 2) * 64, zr);
                lv4.z = mu + sqrtf(fmaxf(expf(lg), 0.002f)) * ev.z;
            }
            {
                float mu = __ldg(emb_b2 + d + 3) + dot64r(emb_w2 + (d + 3) * 64, zr);
                float lg = __ldg(emb_b2 + DLAT + d + 3) + dot64r(emb_w2 + (DLAT + d + 3) * 64, zr);
                lv4.w = mu + sqrtf(fmaxf(expf(lg), 0.002f)) * ev.w;
            }
            outp[l4] = lv4;
            myLat[l4*4+0] = lv4.x; myLat[l4*4+1] = lv4.y;
            myLat[l4*4+2] = lv4.z; myLat[l4*4+3] = lv4.w;
        }
        // key_[b,i,j,:] and alpha[b,i,j] = query . key
        float aj = 0.f;
        for (int a = 0; a < ATTD; a++) {
            float kacc = __ldg(wk_b + a);
            const float4* wk4 = reinterpret_cast<const float4*>(wk_w + a * LDIM);
#pragma unroll
            for (int l4 = 0; l4 < 4; l4++) {
                float4 wv = __ldg(wk4 + l4);
                kacc = fmaf(wv.x, myLat[4*l4+0], kacc);
                kacc = fmaf(wv.y, myLat[4*l4+1], kacc);
                kacc = fmaf(wv.z, myLat[4*l4+2], kacc);
                kacc = fmaf(wv.w, myLat[4*l4+3], kacc);
            }
            aj = fmaf(qv[a], kacc, aj);
        }
        myAl[j] = aj;
    }

    // masked softmax over j
    myAl[i] = -1e9f;
    float m = -3.4e38f;
    for (int j = 0; j < AGN; j++) m = fmaxf(m, myAl[j]);
    float ssum = 0.f;
    for (int j = 0; j < AGN; j++) { float e = expf(myAl[j] - m); myAl[j] = e; ssum += e; }
    float inv = 1.f / ssum;
    for (int j = 0; j < AGN; j++)
        g_alpha[(size_t)(b * AGN + j) * AGN + i] = myAl[j] * inv;  // [b][j][i]
}

// ---------------- K4: message MLP + weighted aggregate + q add (one block per (b,j)) ----------------
__global__ void __launch_bounds__(128) k4_msg(
    const float* __restrict__ msg_w1, const float* __restrict__ msg_b1,
    const float* __restrict__ msg_w2, const float* __restrict__ msg_b2,
    float* __restrict__ ret_q)
{
    __shared__ float lat_s[32 * 16];   // [i][l]
    __shared__ float t_s[32 * 68];     // [i][o], padded
    __shared__ float m1h_s[64];
    __shared__ float al_s[32];
    __shared__ float red_s[16 * 8];
    const int tid = threadIdx.x;
    const int b = blockIdx.x >> 5;
    const int j = blockIdx.x & 31;
    const int bj = b * AGN + j;

    const float* latp = g_lat + (size_t)bj * AGN * LDIM;  // contiguous 512
    for (int idx = tid; idx < 512; idx += 128) lat_s[idx] = latp[idx];
    if (tid < 64) m1h_s[tid] = g_m1h[(size_t)bj * NNHD + tid];
    if (tid < 32) al_s[tid] = g_alpha[(size_t)bj * AGN + tid];
    __syncthreads();

    // layer 1: t[i][o] = lrelu(m1h[o] + W1_lat[o] . lat[i]); 2048 outputs / 128 threads
#pragma unroll
    for (int k = 0; k < 16; k++) {
        int oid = tid + k * 128;
        int i = oid >> 6, o = oid & 63;
        float acc = m1h_s[o];
        const float4* w = reinterpret_cast<const float4*>(msg_w1 + o * 80 + 64);
        const float4* lv = reinterpret_cast<const float4*>(lat_s + i * 16);
#pragma unroll
        for (int l4 = 0; l4 < 4; l4++) {
            float4 wv = __ldg(w + l4);
            float4 la = lv[l4];
            acc = fmaf(wv.x, la.x, acc);
            acc = fmaf(wv.y, la.y, acc);
            acc = fmaf(wv.z, la.z, acc);
            acc = fmaf(wv.w, la.w, acc);
        }
        t_s[i * 68 + o] = acc > 0.f ? acc : 0.01f * acc;
    }
    __syncthreads();

    // layer 2 + alpha-weighted reduce over i
    const int c = tid & 15;
    const int ig = tid >> 4;  // 0..7, 4 i's each
    float b2c = __ldg(msg_b2 + c);
    const float4* w2 = reinterpret_cast<const float4*>(msg_w2 + c * 64);
    float part = 0.f;
    for (int ii = 0; ii < 4; ii++) {
        int i = ig * 4 + ii;
        float acc = b2c;
        const float4* tv = reinterpret_cast<const float4*>(t_s + i * 68);
#pragma unroll
        for (int o4 = 0; o4 < 16; o4++) {
            float4 wv = __ldg(w2 + o4);
            float4 ta = tv[o4];
            acc = fmaf(wv.x, ta.x, acc);
            acc = fmaf(wv.y, ta.y, acc);
            acc = fmaf(wv.z, ta.z, acc);
            acc = fmaf(wv.w, ta.w, acc);
        }
        part = fmaf(al_s[i], acc, part);
    }
    red_s[c * 8 + ig] = part;
    __syncthreads();

    if (tid < 16) {
        float s = 0.f;
#pragma unroll
        for (int g = 0; g < 8; g++) s += red_s[tid * 8 + g];
        ret_q[(size_t)bj * NACTD + tid] = g_q[(size_t)bj * NACTD + tid] + s;
    }
}

// ---------------- host launcher ----------------
extern "C" void kernel_launch(void* const* d_in, const int* in_sizes, int n_in,
                              void* d_out, int out_size)
{
    (void)in_sizes; (void)n_in; (void)out_size;
    const float* inputs  = (const float*)d_in[0];
    const float* hidden  = (const float*)d_in[1];
    const float* eps     = (const float*)d_in[2];
    const float* fc1_w   = (const float*)d_in[3];
    const float* fc1_b   = (const float*)d_in[4];
    const float* gru_wih = (const float*)d_in[5];
    const float* gru_whh = (const float*)d_in[6];
    const float* gru_bih = (const float*)d_in[7];
    const float* gru_bhh = (const float*)d_in[8];
    const float* fc2_w   = (const float*)d_in[9];
    const float* fc2_b   = (const float*)d_in[10];
    const float* emb_w1  = (const float*)d_in[11];
    const float* emb_b1  = (const float*)d_in[12];
    const float* bn_g    = (const float*)d_in[13];
    const float* bn_b    = (const float*)d_in[14];
    const float* emb_w2  = (const float*)d_in[15];
    const float* emb_b2  = (const float*)d_in[16];
    const float* msg_w1  = (const float*)d_in[17];
    const float* msg_b1  = (const float*)d_in[18];
    const float* msg_w2  = (const float*)d_in[19];
    const float* msg_b2  = (const float*)d_in[20];
    const float* wq_w    = (const float*)d_in[21];
    const float* wq_b    = (const float*)d_in[22];
    const float* wk_w    = (const float*)d_in[23];
    const float* wk_b    = (const float*)d_in[24];
    // d_in[25]=bs, d_in[26]=t : compile-time constants, unused

    float* out   = (float*)d_out;
    float* ret_q = out;                          // [32768,16]
    float* h_out = out + (size_t)NROWS * NACTD;  // [32768,64]

    const int K1_SMEM = 128 * 65 * 2 * sizeof(float);  // 66,560 B
    cudaFuncSetAttribute(k1_trunk, cudaFuncAttributeMaxDynamicSharedMemorySize, K1_SMEM);

    k1_trunk<<<NROWS / 128, 128, K1_SMEM>>>(
        inputs, hidden, fc1_w, fc1_b, gru_wih, gru_whh, gru_bih, gru_bhh,
        fc2_w, fc2_b, emb_w1, emb_b1, wq_w, wq_b, msg_w1, msg_b1, h_out);

    k2_bn<<<NNHD, 256>>>(bn_g, bn_b);

    k3_latent<<<NROWS / 128, 128>>>(eps, emb_w2, emb_b2, wk_w, wk_b);

    k4_msg<<<BSZ * AGN, 128>>>(msg_w1, msg_b1, msg_w2, msg_b2, ret_q);
}